// round 13
// baseline (speedup 1.0000x reference)
#include <cuda_runtime.h>
#include <cuda_bf16.h>
#include <cstdint>
#include <cstddef>

// Problem constants (fixed by the reference).
#define NN    100000
#define EE    1600000
#define RR    8
#define DIN   64
#define DOUT  32
#define MT64  1563                 // ceil(100000/64)
#define MPAD64 (MT64 * 64)

// GEMM geometry: K = 576 (8 relations x 64 + 64 self-loop), in 9 chunks of 64.
// A/B chunk row = [hi(64) | lo(64) | pad(8)] = 136 bf16 = 272 B;
// 272 % 128 == 16 -> ldmatrix phases conflict-free.
// Error-compensated product: C = Ah*Bh + Al*Bh + Ah*Bl.
#define KSTRIDE 136
#define NCH     9
#define CH_E    (64 * KSTRIDE)     // 8704 elems = 17408 B (A chunk / B1 chunk)
#define CH2_E   (32 * KSTRIDE)     // 4352 elems =  8704 B (B2 chunk)

// CSR over (dst*8 + etype) keys.
#define NKEY    (NN * RR)          // 800000
#define SCAN_N2 (NKEY + 1)         // 800001
#define SCAN_B  1024
#define SCAN_NB ((SCAN_N2 + SCAN_B - 1) / SCAN_B)  // 782

// ---------------------------------------------------------------------------
// Scratch (__device__ globals; allocation-free rule).
// ---------------------------------------------------------------------------
__device__ __nv_bfloat16 g_Agg[(size_t)MT64 * NCH * CH_E]; // split agg tiles (~245 MB, reused both layers)
__device__ float         g_h1[(size_t)NN * DIN];           // relu(layer1) [N,64]
__device__ __nv_bfloat16 g_B1s[NCH * CH_E];                // layer-1 B chunks
__device__ __nv_bfloat16 g_B2s[NCH * CH2_E];               // layer-2 B chunks
__device__ int           g_cnt[SCAN_N2];                   // CSR offsets
__device__ int           g_pos[NKEY];                      // scatter cursors
__device__ int           g_bsum[SCAN_NB];                  // scan partials
__device__ int           g_eidx[EE];                       // src per edge, bucket-sorted

// ---------------------------------------------------------------------------
// PTX helpers (base sm_103-safe: ldmatrix + mma.sync only).
// ---------------------------------------------------------------------------
__device__ __forceinline__ uint32_t smem_u32(const void* p) {
    uint32_t a;
    asm("{ .reg .u64 t; cvta.to.shared.u64 t, %1; cvt.u32.u64 %0, t; }" : "=r"(a) : "l"(p));
    return a;
}

#define LDSM4(r0, r1, r2, r3, addr)                                             \
    asm volatile("ldmatrix.sync.aligned.m8n8.x4.shared.b16 {%0,%1,%2,%3}, [%4];" \
                 : "=r"(r0), "=r"(r1), "=r"(r2), "=r"(r3) : "r"(addr))

#define MMA16816(c0, c1, c2, c3, a0, a1, a2, a3, b0, b1)                        \
    asm volatile("mma.sync.aligned.m16n8k16.row.col.f32.bf16.bf16.f32 "          \
                 "{%0,%1,%2,%3},{%4,%5,%6,%7},{%8,%9},{%0,%1,%2,%3};"            \
                 : "+f"(c0), "+f"(c1), "+f"(c2), "+f"(c3)                        \
                 : "r"(a0), "r"(a1), "r"(a2), "r"(a3), "r"(b0), "r"(b1))

// ---------------------------------------------------------------------------
// CSR build over (dst*8 + ety).
// ---------------------------------------------------------------------------
__global__ void zero_cnt_k()
{
    int t = blockIdx.x * blockDim.x + threadIdx.x;
    if (t < SCAN_N2) g_cnt[t] = 0;
}

__global__ void hist_k(const int* __restrict__ dst, const int* __restrict__ ety, int Ne)
{
    int e = blockIdx.x * blockDim.x + threadIdx.x;
    if (e < Ne) atomicAdd(&g_cnt[dst[e] * RR + ety[e] + 1], 1);
}

__global__ void scan1_k()
{
    __shared__ int sh[SCAN_B];
    int i = blockIdx.x * SCAN_B + threadIdx.x;
    int v = (i < SCAN_N2) ? g_cnt[i] : 0;
    sh[threadIdx.x] = v;
    __syncthreads();
#pragma unroll
    for (int off = 1; off < SCAN_B; off <<= 1) {
        int t = (threadIdx.x >= off) ? sh[threadIdx.x - off] : 0;
        __syncthreads();
        sh[threadIdx.x] += t;
        __syncthreads();
    }
    if (i < SCAN_N2) g_cnt[i] = sh[threadIdx.x];
    if (threadIdx.x == SCAN_B - 1) g_bsum[blockIdx.x] = sh[SCAN_B - 1];
}

__global__ void scan2_k()
{
    __shared__ int sh[1024];
    int t = threadIdx.x;
    int v = (t < SCAN_NB) ? g_bsum[t] : 0;
    sh[t] = v;
    __syncthreads();
#pragma unroll
    for (int off = 1; off < 1024; off <<= 1) {
        int u = (t >= off) ? sh[t - off] : 0;
        __syncthreads();
        sh[t] += u;
        __syncthreads();
    }
    if (t < SCAN_NB) g_bsum[t] = sh[t] - v;   // exclusive block base
}

__global__ void scan3_k()
{
    int i = blockIdx.x * blockDim.x + threadIdx.x;
    if (i < SCAN_N2) {
        int v = g_cnt[i] + g_bsum[i / SCAN_B];
        g_cnt[i] = v;
        if (i < NKEY) g_pos[i] = v;
    }
}

__global__ void scatter_k(const int* __restrict__ src, const int* __restrict__ dst,
                          const int* __restrict__ ety, int Ne)
{
    int e = blockIdx.x * blockDim.x + threadIdx.x;
    if (e >= Ne) return;
    int p = atomicAdd(&g_pos[dst[e] * RR + ety[e]], 1);
    g_eidx[p] = src[e];
}

// ---------------------------------------------------------------------------
// Pack weights -> B chunks [c][n][hi64|lo64|pad8] bf16.
// k = c*64 + kk; c<8 -> relation c input dim kk; c==8 -> self-loop.
// ---------------------------------------------------------------------------
__global__ void pack_B_k(const float* __restrict__ W1, const float* __restrict__ Ws1,
                         const float* __restrict__ W2, const float* __restrict__ Ws2)
{
    int u = blockIdx.x * blockDim.x + threadIdx.x;
    const int tot1 = NCH * 64 * 64;      // 36864
    const int tot2 = NCH * 32 * 64;      // 18432
    if (u >= tot1 + tot2) return;
    __nv_bfloat16* row;
    float w;
    int kk;
    if (u < tot1) {
        int c = u >> 12, rem = u & 4095;
        int n = rem >> 6; kk = rem & 63;
        w = (c < 8) ? W1[((size_t)(c * 64 + kk)) * 64 + n]
                    : Ws1[(size_t)kk * 64 + n];
        row = g_B1s + (size_t)c * CH_E + n * KSTRIDE;
    } else {
        int u2 = u - tot1;
        int c = u2 / 2048, rem = u2 % 2048;
        int n = rem >> 6; kk = rem & 63;
        w = (c < 8) ? W2[((size_t)(c * 64 + kk)) * 32 + n]
                    : Ws2[(size_t)kk * 32 + n];
        row = g_B2s + (size_t)c * CH2_E + n * KSTRIDE;
    }
    __nv_bfloat16 h = __float2bfloat16(w);
    __nv_bfloat16 l = __float2bfloat16(w - __bfloat162float(h));
    row[kk]      = h;
    row[64 + kk] = l;
    if (kk < 8) row[128 + kk] = __float2bfloat16(0.f);
}

// ---------------------------------------------------------------------------
// Gather + split: one 16-lane group per (node, chunk). Chunk<8: sum X[src]
// over the (n, r) CSR bucket; chunk==8: copy X[n] (self-loop). Accumulate in
// registers, split to bf16 hi/lo, write A-tile layout directly.
// X is L2-resident (25.6 MB).
// ---------------------------------------------------------------------------
__global__ void __launch_bounds__(256)
gather_k(const float* __restrict__ X, int Nn)
{
    int gid = blockIdx.x * blockDim.x + threadIdx.x;
    int grp = gid >> 4;
    if (grp >= Nn * NCH) return;
    int l = gid & 15;
    int n = grp / NCH;
    int c = grp - n * NCH;

    float4 acc = make_float4(0.f, 0.f, 0.f, 0.f);
    if (c == 8) {
        acc = *reinterpret_cast<const float4*>(X + (size_t)n * 64 + l * 4);
    } else {
        int key = n * RR + c;
        int beg = g_cnt[key], end = g_cnt[key + 1];
        for (int e = beg; e < end; e++) {
            int s = __ldg(g_eidx + e);
            float4 v = *reinterpret_cast<const float4*>(X + (size_t)s * 64 + l * 4);
            acc.x += v.x; acc.y += v.y; acc.z += v.z; acc.w += v.w;
        }
    }

    __nv_bfloat16 hx = __float2bfloat16(acc.x), hy = __float2bfloat16(acc.y);
    __nv_bfloat16 hz = __float2bfloat16(acc.z), hw = __float2bfloat16(acc.w);
    __nv_bfloat16 lx = __float2bfloat16(acc.x - __bfloat162float(hx));
    __nv_bfloat16 ly = __float2bfloat16(acc.y - __bfloat162float(hy));
    __nv_bfloat16 lz = __float2bfloat16(acc.z - __bfloat162float(hz));
    __nv_bfloat16 lw = __float2bfloat16(acc.w - __bfloat162float(hw));

    __nv_bfloat16* row = g_Agg + ((size_t)(n >> 6) * NCH + c) * CH_E + (size_t)(n & 63) * KSTRIDE;
    __nv_bfloat162 h01; h01.x = hx; h01.y = hy;
    __nv_bfloat162 h23; h23.x = hz; h23.y = hw;
    __nv_bfloat162 l01; l01.x = lx; l01.y = ly;
    __nv_bfloat162 l23; l23.x = lz; l23.y = lw;
    *reinterpret_cast<__nv_bfloat162*>(row + l * 4)          = h01;
    *reinterpret_cast<__nv_bfloat162*>(row + l * 4 + 2)      = h23;
    *reinterpret_cast<__nv_bfloat162*>(row + 64 + l * 4)     = l01;
    *reinterpret_cast<__nv_bfloat162*>(row + 64 + l * 4 + 2) = l23;
    if (l < 2) {
        __nv_bfloat162 z; z.x = __float2bfloat16(0.f); z.y = z.x;
        *reinterpret_cast<__nv_bfloat162*>(row + 128 + l * 4)     = z;
        *reinterpret_cast<__nv_bfloat162*>(row + 128 + l * 4 + 2) = z;
    }
}

// ---------------------------------------------------------------------------
// GEMM layer 1: h1 = relu(Agg[64x576] @ B1[576x64] + b1). K-chunk loop,
// C accumulates in registers across chunks. Warps 4(m) x 2(n=32).
// ---------------------------------------------------------------------------
__global__ void __launch_bounds__(256)
gemm1_k(const float* __restrict__ b1, int Nn)
{
    __shared__ __nv_bfloat16 sm[2 * CH_E];   // 34816 B static
    const int tid  = threadIdx.x;
    const int lane = tid & 31;
    const int wid  = tid >> 5;
    const int wm   = wid & 3;
    const int wn   = wid >> 2;
    const int m0   = blockIdx.x * 64;

    const uint32_t smA = smem_u32(sm);
    const uint32_t smB = smA + CH_E * 2;
    const uint32_t aAddr  = smA + (uint32_t)(wm * 16 + (lane & 15)) * (KSTRIDE * 2)
                          + (uint32_t)((lane >> 4) << 4);
    const uint32_t bAddr0 = smB + (uint32_t)(wn * 32 + ((lane >> 4) << 3) + (lane & 7)) * (KSTRIDE * 2)
                          + (uint32_t)(((lane >> 3) & 1) << 4);
    const uint32_t bAddr1 = bAddr0 + 16 * (KSTRIDE * 2);

    float c[4][4];
#pragma unroll
    for (int i = 0; i < 4; i++)
#pragma unroll
        for (int j = 0; j < 4; j++) c[i][j] = 0.f;

    for (int ch = 0; ch < NCH; ch++) {
        __syncthreads();
        {
            const float4* srcA = reinterpret_cast<const float4*>(
                g_Agg + ((size_t)blockIdx.x * NCH + ch) * CH_E);
            const float4* srcB = reinterpret_cast<const float4*>(g_B1s + (size_t)ch * CH_E);
            float4* dstA = reinterpret_cast<float4*>(sm);
            float4* dstB = reinterpret_cast<float4*>(sm + CH_E);
            for (int i = tid; i < CH_E / 8; i += 256) { dstA[i] = srcA[i]; dstB[i] = srcB[i]; }
        }
        __syncthreads();

#pragma unroll
        for (int s = 0; s < 12; s++) {
            const int combo = s >> 2;            // 0:(h,h) 1:(l,h) 2:(h,l)
            const int ks    = s & 3;
            const uint32_t ao = (combo == 1 ? 128u : 0u) + (uint32_t)ks * 32u;
            const uint32_t bo = (combo == 2 ? 128u : 0u) + (uint32_t)ks * 32u;
            uint32_t a[4], b0[4], b1v[4];
            LDSM4(a[0], a[1], a[2], a[3], aAddr + ao);
            LDSM4(b0[0], b0[1], b0[2], b0[3], bAddr0 + bo);
            LDSM4(b1v[0], b1v[1], b1v[2], b1v[3], bAddr1 + bo);
            MMA16816(c[0][0], c[0][1], c[0][2], c[0][3], a[0], a[1], a[2], a[3], b0[0], b0[1]);
            MMA16816(c[1][0], c[1][1], c[1][2], c[1][3], a[0], a[1], a[2], a[3], b0[2], b0[3]);
            MMA16816(c[2][0], c[2][1], c[2][2], c[2][3], a[0], a[1], a[2], a[3], b1v[0], b1v[1]);
            MMA16816(c[3][0], c[3][1], c[3][2], c[3][3], a[0], a[1], a[2], a[3], b1v[2], b1v[3]);
        }
    }

    const int colBase = wn * 32 + 2 * (lane & 3);
    const int row0 = m0 + wm * 16 + (lane >> 2);
#pragma unroll
    for (int j = 0; j < 4; j++) {
        int col = colBase + j * 8;
        float bx = __ldg(b1 + col), by = __ldg(b1 + col + 1);
        if (row0 < Nn)
            *reinterpret_cast<float2*>(g_h1 + (size_t)row0 * 64 + col) =
                make_float2(fmaxf(c[j][0] + bx, 0.f), fmaxf(c[j][1] + by, 0.f));
        if (row0 + 8 < Nn)
            *reinterpret_cast<float2*>(g_h1 + (size_t)(row0 + 8) * 64 + col) =
                make_float2(fmaxf(c[j][2] + bx, 0.f), fmaxf(c[j][3] + by, 0.f));
    }
}

// ---------------------------------------------------------------------------
// GEMM layer 2: out = Agg2[64x576] @ B2[576x32] + b2. Warps 4(m) x 2(n=16).
// ---------------------------------------------------------------------------
__global__ void __launch_bounds__(256)
gemm2_k(const float* __restrict__ b2, float* __restrict__ out, int Nn)
{
    __shared__ __nv_bfloat16 sm[CH_E + CH2_E];   // 26112 B
    const int tid  = threadIdx.x;
    const int lane = tid & 31;
    const int wid  = tid >> 5;
    const int wm   = wid & 3;
    const int wn   = wid >> 2;
    const int m0   = blockIdx.x * 64;

    const uint32_t smA = smem_u32(sm);
    const uint32_t smB = smA + CH_E * 2;
    const uint32_t aAddr  = smA + (uint32_t)(wm * 16 + (lane & 15)) * (KSTRIDE * 2)
                          + (uint32_t)((lane >> 4) << 4);
    const uint32_t bAddr0 = smB + (uint32_t)(wn * 16 + ((lane >> 4) << 3) + (lane & 7)) * (KSTRIDE * 2)
                          + (uint32_t)(((lane >> 3) & 1) << 4);

    float c[2][4];
#pragma unroll
    for (int i = 0; i < 2; i++)
#pragma unroll
        for (int j = 0; j < 4; j++) c[i][j] = 0.f;

    for (int ch = 0; ch < NCH; ch++) {
        __syncthreads();
        {
            const float4* srcA = reinterpret_cast<const float4*>(
                g_Agg + ((size_t)blockIdx.x * NCH + ch) * CH_E);
            float4* dstA = reinterpret_cast<float4*>(sm);
            for (int i = tid; i < CH_E / 8; i += 256) dstA[i] = srcA[i];
            const float4* srcB = reinterpret_cast<const float4*>(g_B2s + (size_t)ch * CH2_E);
            float4* dstB = reinterpret_cast<float4*>(sm + CH_E);
            for (int i = tid; i < CH2_E / 8; i += 256) dstB[i] = srcB[i];
        }
        __syncthreads();

#pragma unroll
        for (int s = 0; s < 12; s++) {
            const int combo = s >> 2;
            const int ks    = s & 3;
            const uint32_t ao = (combo == 1 ? 128u : 0u) + (uint32_t)ks * 32u;
            const uint32_t bo = (combo == 2 ? 128u : 0u) + (uint32_t)ks * 32u;
            uint32_t a[4], b0[4];
            LDSM4(a[0], a[1], a[2], a[3], aAddr + ao);
            LDSM4(b0[0], b0[1], b0[2], b0[3], bAddr0 + bo);
            MMA16816(c[0][0], c[0][1], c[0][2], c[0][3], a[0], a[1], a[2], a[3], b0[0], b0[1]);
            MMA16816(c[1][0], c[1][1], c[1][2], c[1][3], a[0], a[1], a[2], a[3], b0[2], b0[3]);
        }
    }

    const int colBase = wn * 16 + 2 * (lane & 3);
    const int row0 = m0 + wm * 16 + (lane >> 2);
#pragma unroll
    for (int j = 0; j < 2; j++) {
        int col = colBase + j * 8;
        float bx = __ldg(b2 + col), by = __ldg(b2 + col + 1);
        if (row0 < Nn)
            *reinterpret_cast<float2*>(out + (size_t)row0 * 32 + col) =
                make_float2(c[j][0] + bx, c[j][1] + by);
        if (row0 + 8 < Nn)
            *reinterpret_cast<float2*>(out + (size_t)(row0 + 8) * 32 + col) =
                make_float2(c[j][2] + bx, c[j][3] + by);
    }
}

// ---------------------------------------------------------------------------
// kernel_launch
// ---------------------------------------------------------------------------
extern "C" void kernel_launch(void* const* d_in, const int* in_sizes, int n_in,
                              void* d_out, int out_size)
{
    const float* feat = (const float*)d_in[0];
    const int*   src  = (const int*)  d_in[1];
    const int*   dst  = (const int*)  d_in[2];
    const int*   ety  = (const int*)  d_in[3];
    const float* W1   = (const float*)d_in[4];
    const float* Ws1  = (const float*)d_in[5];
    const float* b1   = (const float*)d_in[6];
    const float* W2   = (const float*)d_in[7];
    const float* Ws2  = (const float*)d_in[8];
    const float* b2   = (const float*)d_in[9];
    float* out = (float*)d_out;

    int Nn = in_sizes[0] / DIN;
    int Ne = in_sizes[1];
    int MT = (Nn + 63) / 64;

    float* pH1;
    cudaGetSymbolAddress((void**)&pH1, g_h1);

    // CSR over (dst, rel).
    zero_cnt_k<<<(SCAN_N2 + 255) / 256, 256>>>();
    hist_k<<<(Ne + 255) / 256, 256>>>(dst, ety, Ne);
    scan1_k<<<SCAN_NB, SCAN_B>>>();
    scan2_k<<<1, 1024>>>();
    scan3_k<<<(SCAN_N2 + 255) / 256, 256>>>();
    scatter_k<<<(Ne + 255) / 256, 256>>>(src, dst, ety, Ne);

    pack_B_k<<<(NCH * 64 * 64 + NCH * 32 * 64 + 255) / 256, 256>>>(W1, Ws1, W2, Ws2);

    // Layer 1: aggregate feat (L2-resident) -> split agg -> GEMM (+bias, relu).
    gather_k<<<(Nn * NCH * 16 + 255) / 256, 256>>>(feat, Nn);
    gemm1_k<<<MT, 256>>>(b1, Nn);

    // Layer 2: aggregate h1 (L2-resident) -> split agg -> GEMM (+bias).
    gather_k<<<(Nn * NCH * 16 + 255) / 256, 256>>>(pH1, Nn);
    gemm2_k<<<MT, 256>>>(b2, out, Nn);
}

// round 14
// speedup vs baseline: 1.2899x; 1.2899x over previous
#include <cuda_runtime.h>
#include <cuda_bf16.h>
#include <cstdint>
#include <cstddef>

// Problem constants (fixed by the reference).
#define NN    100000
#define EE    1600000
#define RR    8
#define DIN   64
#define DOUT  32

// GEMM geometry: K = 576 (8 relations x 64 + 64 self-loop), in 9 chunks of 64.
// A/B chunk row = [hi(64) | lo(64) | pad(8)] = 136 bf16 = 272 B;
// 272 % 128 == 16 -> ldmatrix phases conflict-free.
// Error-compensated product: C = Ah*Bh + Al*Bh + Ah*Bl.
#define KSTRIDE 136
#define NCH     9
#define CH_E    (64 * KSTRIDE)     // 8704 elems = 17408 B (A chunk / B1 chunk)
#define CH2_E   (32 * KSTRIDE)     // 4352 elems =  8704 B (B2 chunk)

// CSR over (dst*8 + etype) keys.
#define NKEY    (NN * RR)          // 800000
#define SCAN_N2 (NKEY + 1)         // 800001
#define SCAN_B  1024
#define SCAN_NB ((SCAN_N2 + SCAN_B - 1) / SCAN_B)  // 782

// ---------------------------------------------------------------------------
// Scratch (__device__ globals; allocation-free rule).
// ---------------------------------------------------------------------------
__device__ float         g_h1[(size_t)NN * DIN];    // relu(layer1) [N,64] (L2-resident)
__device__ __nv_bfloat16 g_B1s[NCH * CH_E];         // layer-1 B chunks
__device__ __nv_bfloat16 g_B2s[NCH * CH2_E];        // layer-2 B chunks
__device__ int           g_cnt[SCAN_N2];            // CSR offsets
__device__ int           g_pos[NKEY];               // scatter cursors
__device__ int           g_bsum[SCAN_NB];           // scan partials
__device__ int           g_eidx[EE];                // src per edge, bucket-sorted

// ---------------------------------------------------------------------------
// PTX helpers (base sm_103-safe: ldmatrix + mma.sync only).
// ---------------------------------------------------------------------------
__device__ __forceinline__ uint32_t smem_u32(const void* p) {
    uint32_t a;
    asm("{ .reg .u64 t; cvta.to.shared.u64 t, %1; cvt.u32.u64 %0, t; }" : "=r"(a) : "l"(p));
    return a;
}

#define LDSM4(r0, r1, r2, r3, addr)                                             \
    asm volatile("ldmatrix.sync.aligned.m8n8.x4.shared.b16 {%0,%1,%2,%3}, [%4];" \
                 : "=r"(r0), "=r"(r1), "=r"(r2), "=r"(r3) : "r"(addr))

#define MMA16816(c0, c1, c2, c3, a0, a1, a2, a3, b0, b1)                        \
    asm volatile("mma.sync.aligned.m16n8k16.row.col.f32.bf16.bf16.f32 "          \
                 "{%0,%1,%2,%3},{%4,%5,%6,%7},{%8,%9},{%0,%1,%2,%3};"            \
                 : "+f"(c0), "+f"(c1), "+f"(c2), "+f"(c3)                        \
                 : "r"(a0), "r"(a1), "r"(a2), "r"(a3), "r"(b0), "r"(b1))

// ---------------------------------------------------------------------------
// CSR build over (dst*8 + ety).
// ---------------------------------------------------------------------------
__global__ void zero_cnt_k()
{
    int t = blockIdx.x * blockDim.x + threadIdx.x;
    if (t < SCAN_N2) g_cnt[t] = 0;
}

__global__ void hist_k(const int* __restrict__ dst, const int* __restrict__ ety, int Ne)
{
    int e = blockIdx.x * blockDim.x + threadIdx.x;
    if (e < Ne) atomicAdd(&g_cnt[dst[e] * RR + ety[e] + 1], 1);
}

__global__ void scan1_k()
{
    __shared__ int sh[SCAN_B];
    int i = blockIdx.x * SCAN_B + threadIdx.x;
    int v = (i < SCAN_N2) ? g_cnt[i] : 0;
    sh[threadIdx.x] = v;
    __syncthreads();
#pragma unroll
    for (int off = 1; off < SCAN_B; off <<= 1) {
        int t = (threadIdx.x >= off) ? sh[threadIdx.x - off] : 0;
        __syncthreads();
        sh[threadIdx.x] += t;
        __syncthreads();
    }
    if (i < SCAN_N2) g_cnt[i] = sh[threadIdx.x];
    if (threadIdx.x == SCAN_B - 1) g_bsum[blockIdx.x] = sh[SCAN_B - 1];
}

__global__ void scan2_k()
{
    __shared__ int sh[1024];
    int t = threadIdx.x;
    int v = (t < SCAN_NB) ? g_bsum[t] : 0;
    sh[t] = v;
    __syncthreads();
#pragma unroll
    for (int off = 1; off < 1024; off <<= 1) {
        int u = (t >= off) ? sh[t - off] : 0;
        __syncthreads();
        sh[t] += u;
        __syncthreads();
    }
    if (t < SCAN_NB) g_bsum[t] = sh[t] - v;   // exclusive block base
}

__global__ void scan3_k()
{
    int i = blockIdx.x * blockDim.x + threadIdx.x;
    if (i < SCAN_N2) {
        int v = g_cnt[i] + g_bsum[i / SCAN_B];
        g_cnt[i] = v;
        if (i < NKEY) g_pos[i] = v;
    }
}

__global__ void scatter_k(const int* __restrict__ src, const int* __restrict__ dst,
                          const int* __restrict__ ety, int Ne)
{
    int e = blockIdx.x * blockDim.x + threadIdx.x;
    if (e >= Ne) return;
    int p = atomicAdd(&g_pos[dst[e] * RR + ety[e]], 1);
    g_eidx[p] = src[e];
}

// ---------------------------------------------------------------------------
// Pack weights -> B chunks [c][n][hi64|lo64|pad8] bf16.
// ---------------------------------------------------------------------------
__global__ void pack_B_k(const float* __restrict__ W1, const float* __restrict__ Ws1,
                         const float* __restrict__ W2, const float* __restrict__ Ws2)
{
    int u = blockIdx.x * blockDim.x + threadIdx.x;
    const int tot1 = NCH * 64 * 64;      // 36864
    const int tot2 = NCH * 32 * 64;      // 18432
    if (u >= tot1 + tot2) return;
    __nv_bfloat16* row;
    float w;
    int kk;
    if (u < tot1) {
        int c = u >> 12, rem = u & 4095;
        int n = rem >> 6; kk = rem & 63;
        w = (c < 8) ? W1[((size_t)(c * 64 + kk)) * 64 + n]
                    : Ws1[(size_t)kk * 64 + n];
        row = g_B1s + (size_t)c * CH_E + n * KSTRIDE;
    } else {
        int u2 = u - tot1;
        int c = u2 / 2048, rem = u2 % 2048;
        int n = rem >> 6; kk = rem & 63;
        w = (c < 8) ? W2[((size_t)(c * 64 + kk)) * 32 + n]
                    : Ws2[(size_t)kk * 32 + n];
        row = g_B2s + (size_t)c * CH2_E + n * KSTRIDE;
    }
    __nv_bfloat16 h = __float2bfloat16(w);
    __nv_bfloat16 l = __float2bfloat16(w - __bfloat162float(h));
    row[kk]      = h;
    row[64 + kk] = l;
    if (kk < 8) row[128 + kk] = __float2bfloat16(0.f);
}

// ---------------------------------------------------------------------------
// Shared device routine: gather one (node, chunk) bucket sum from X and write
// the split bf16 row into the smem A tile.
// ---------------------------------------------------------------------------
__device__ __forceinline__ void gather_row(const float* __restrict__ X,
                                           __nv_bfloat16* __restrict__ smA,
                                           int n, int m, int ch, int l, int Nn)
{
    float4 acc = make_float4(0.f, 0.f, 0.f, 0.f);
    if (n < Nn) {
        if (ch == 8) {
            acc = *reinterpret_cast<const float4*>(X + (size_t)n * 64 + l * 4);
        } else {
            int key = n * RR + ch;
            int beg = __ldg(g_cnt + key), end = __ldg(g_cnt + key + 1);
            for (int e = beg; e < end; e++) {
                int s = __ldg(g_eidx + e);
                float4 v = *reinterpret_cast<const float4*>(X + (size_t)s * 64 + l * 4);
                acc.x += v.x; acc.y += v.y; acc.z += v.z; acc.w += v.w;
            }
        }
    }
    __nv_bfloat16 hx = __float2bfloat16(acc.x), hy = __float2bfloat16(acc.y);
    __nv_bfloat16 hz = __float2bfloat16(acc.z), hw = __float2bfloat16(acc.w);
    __nv_bfloat162 h01; h01.x = hx; h01.y = hy;
    __nv_bfloat162 h23; h23.x = hz; h23.y = hw;
    __nv_bfloat162 l01; l01.x = __float2bfloat16(acc.x - __bfloat162float(hx));
    l01.y = __float2bfloat16(acc.y - __bfloat162float(hy));
    __nv_bfloat162 l23; l23.x = __float2bfloat16(acc.z - __bfloat162float(hz));
    l23.y = __float2bfloat16(acc.w - __bfloat162float(hw));

    __nv_bfloat16* row = smA + (size_t)m * KSTRIDE;
    *reinterpret_cast<__nv_bfloat162*>(row + l * 4)          = h01;
    *reinterpret_cast<__nv_bfloat162*>(row + l * 4 + 2)      = h23;
    *reinterpret_cast<__nv_bfloat162*>(row + 64 + l * 4)     = l01;
    *reinterpret_cast<__nv_bfloat162*>(row + 64 + l * 4 + 2) = l23;
    if (l < 2) {
        __nv_bfloat162 z; z.x = __float2bfloat16(0.f); z.y = z.x;
        *reinterpret_cast<__nv_bfloat162*>(row + 128 + l * 4)     = z;
        *reinterpret_cast<__nv_bfloat162*>(row + 128 + l * 4 + 2) = z;
    }
}

// ---------------------------------------------------------------------------
// Fused layer 1: per 64-node tile, per chunk: gather A into smem + copy B
// chunk, then 12-step compensated MMA; C accumulates across chunks.
// Epilogue: +bias, relu -> g_h1.
// ---------------------------------------------------------------------------
__global__ void __launch_bounds__(256)
fused1_k(const float* __restrict__ X, const float* __restrict__ b1, int Nn)
{
    __shared__ __nv_bfloat16 sm[2 * CH_E];   // A | B, 34816 B
    const int tid  = threadIdx.x;
    const int lane = tid & 31;
    const int wid  = tid >> 5;
    const int wm   = wid & 3;
    const int wn   = wid >> 2;
    const int m0   = blockIdx.x * 64;
    const int grp  = tid >> 4;               // 16 gather groups
    const int gl   = tid & 15;

    const uint32_t smA = smem_u32(sm);
    const uint32_t smB = smA + CH_E * 2;
    const uint32_t aAddr  = smA + (uint32_t)(wm * 16 + (lane & 15)) * (KSTRIDE * 2)
                          + (uint32_t)((lane >> 4) << 4);
    const uint32_t bAddr0 = smB + (uint32_t)(wn * 32 + ((lane >> 4) << 3) + (lane & 7)) * (KSTRIDE * 2)
                          + (uint32_t)(((lane >> 3) & 1) << 4);
    const uint32_t bAddr1 = bAddr0 + 16 * (KSTRIDE * 2);

    float c[4][4];
#pragma unroll
    for (int i = 0; i < 4; i++)
#pragma unroll
        for (int j = 0; j < 4; j++) c[i][j] = 0.f;

    for (int ch = 0; ch < NCH; ch++) {
        __syncthreads();                     // previous MMA reads done
        {
            const float4* srcB = reinterpret_cast<const float4*>(g_B1s + (size_t)ch * CH_E);
            float4* dstB = reinterpret_cast<float4*>(sm + CH_E);
            for (int i = tid; i < CH_E / 8; i += 256) dstB[i] = srcB[i];
        }
#pragma unroll
        for (int i = 0; i < 4; i++) {
            int m = i * 16 + grp;            // 0..63
            gather_row(X, sm, m0 + m, m, ch, gl, Nn);
        }
        __syncthreads();

#pragma unroll
        for (int s = 0; s < 12; s++) {
            const int combo = s >> 2;        // 0:(h,h) 1:(l,h) 2:(h,l)
            const int ks    = s & 3;
            const uint32_t ao = (combo == 1 ? 128u : 0u) + (uint32_t)ks * 32u;
            const uint32_t bo = (combo == 2 ? 128u : 0u) + (uint32_t)ks * 32u;
            uint32_t a[4], b0[4], b1v[4];
            LDSM4(a[0], a[1], a[2], a[3], aAddr + ao);
            LDSM4(b0[0], b0[1], b0[2], b0[3], bAddr0 + bo);
            LDSM4(b1v[0], b1v[1], b1v[2], b1v[3], bAddr1 + bo);
            MMA16816(c[0][0], c[0][1], c[0][2], c[0][3], a[0], a[1], a[2], a[3], b0[0], b0[1]);
            MMA16816(c[1][0], c[1][1], c[1][2], c[1][3], a[0], a[1], a[2], a[3], b0[2], b0[3]);
            MMA16816(c[2][0], c[2][1], c[2][2], c[2][3], a[0], a[1], a[2], a[3], b1v[0], b1v[1]);
            MMA16816(c[3][0], c[3][1], c[3][2], c[3][3], a[0], a[1], a[2], a[3], b1v[2], b1v[3]);
        }
    }

    const int colBase = wn * 32 + 2 * (lane & 3);
    const int row0 = m0 + wm * 16 + (lane >> 2);
#pragma unroll
    for (int j = 0; j < 4; j++) {
        int col = colBase + j * 8;
        float bx = __ldg(b1 + col), by = __ldg(b1 + col + 1);
        if (row0 < Nn)
            *reinterpret_cast<float2*>(g_h1 + (size_t)row0 * 64 + col) =
                make_float2(fmaxf(c[j][0] + bx, 0.f), fmaxf(c[j][1] + by, 0.f));
        if (row0 + 8 < Nn)
            *reinterpret_cast<float2*>(g_h1 + (size_t)(row0 + 8) * 64 + col) =
                make_float2(fmaxf(c[j][2] + bx, 0.f), fmaxf(c[j][3] + by, 0.f));
    }
}

// ---------------------------------------------------------------------------
// Fused layer 2: same structure, X = g_h1, B2 chunks (32 cols), +bias -> out.
// ---------------------------------------------------------------------------
__global__ void __launch_bounds__(256)
fused2_k(const float* __restrict__ b2, float* __restrict__ out, int Nn)
{
    __shared__ __nv_bfloat16 sm[CH_E + CH2_E];   // 26112 B
    const int tid  = threadIdx.x;
    const int lane = tid & 31;
    const int wid  = tid >> 5;
    const int wm   = wid & 3;
    const int wn   = wid >> 2;
    const int m0   = blockIdx.x * 64;
    const int grp  = tid >> 4;
    const int gl   = tid & 15;

    const uint32_t smA = smem_u32(sm);
    const uint32_t smB = smA + CH_E * 2;
    const uint32_t aAddr  = smA + (uint32_t)(wm * 16 + (lane & 15)) * (KSTRIDE * 2)
                          + (uint32_t)((lane >> 4) << 4);
    const uint32_t bAddr0 = smB + (uint32_t)(wn * 16 + ((lane >> 4) << 3) + (lane & 7)) * (KSTRIDE * 2)
                          + (uint32_t)(((lane >> 3) & 1) << 4);

    float c[2][4];
#pragma unroll
    for (int i = 0; i < 2; i++)
#pragma unroll
        for (int j = 0; j < 4; j++) c[i][j] = 0.f;

    for (int ch = 0; ch < NCH; ch++) {
        __syncthreads();
        {
            const float4* srcB = reinterpret_cast<const float4*>(g_B2s + (size_t)ch * CH2_E);
            float4* dstB = reinterpret_cast<float4*>(sm + CH_E);
            for (int i = tid; i < CH2_E / 8; i += 256) dstB[i] = srcB[i];
        }
#pragma unroll
        for (int i = 0; i < 4; i++) {
            int m = i * 16 + grp;
            gather_row(g_h1, sm, m0 + m, m, ch, gl, Nn);
        }
        __syncthreads();

#pragma unroll
        for (int s = 0; s < 12; s++) {
            const int combo = s >> 2;
            const int ks    = s & 3;
            const uint32_t ao = (combo == 1 ? 128u : 0u) + (uint32_t)ks * 32u;
            const uint32_t bo = (combo == 2 ? 128u : 0u) + (uint32_t)ks * 32u;
            uint32_t a[4], b0[4];
            LDSM4(a[0], a[1], a[2], a[3], aAddr + ao);
            LDSM4(b0[0], b0[1], b0[2], b0[3], bAddr0 + bo);
            MMA16816(c[0][0], c[0][1], c[0][2], c[0][3], a[0], a[1], a[2], a[3], b0[0], b0[1]);
            MMA16816(c[1][0], c[1][1], c[1][2], c[1][3], a[0], a[1], a[2], a[3], b0[2], b0[3]);
        }
    }

    const int colBase = wn * 16 + 2 * (lane & 3);
    const int row0 = m0 + wm * 16 + (lane >> 2);
#pragma unroll
    for (int j = 0; j < 2; j++) {
        int col = colBase + j * 8;
        float bx = __ldg(b2 + col), by = __ldg(b2 + col + 1);
        if (row0 < Nn)
            *reinterpret_cast<float2*>(out + (size_t)row0 * 32 + col) =
                make_float2(c[j][0] + bx, c[j][1] + by);
        if (row0 + 8 < Nn)
            *reinterpret_cast<float2*>(out + (size_t)(row0 + 8) * 32 + col) =
                make_float2(c[j][2] + bx, c[j][3] + by);
    }
}

// ---------------------------------------------------------------------------
// kernel_launch
// ---------------------------------------------------------------------------
extern "C" void kernel_launch(void* const* d_in, const int* in_sizes, int n_in,
                              void* d_out, int out_size)
{
    const float* feat = (const float*)d_in[0];
    const int*   src  = (const int*)  d_in[1];
    const int*   dst  = (const int*)  d_in[2];
    const int*   ety  = (const int*)  d_in[3];
    const float* W1   = (const float*)d_in[4];
    const float* Ws1  = (const float*)d_in[5];
    const float* b1   = (const float*)d_in[6];
    const float* W2   = (const float*)d_in[7];
    const float* Ws2  = (const float*)d_in[8];
    const float* b2   = (const float*)d_in[9];
    float* out = (float*)d_out;

    int Nn = in_sizes[0] / DIN;
    int Ne = in_sizes[1];
    int MT = (Nn + 63) / 64;

    // CSR over (dst, rel).
    zero_cnt_k<<<(SCAN_N2 + 255) / 256, 256>>>();
    hist_k<<<(Ne + 255) / 256, 256>>>(dst, ety, Ne);
    scan1_k<<<SCAN_NB, SCAN_B>>>();
    scan2_k<<<1, 1024>>>();
    scan3_k<<<(SCAN_N2 + 255) / 256, 256>>>();
    scatter_k<<<(Ne + 255) / 256, 256>>>(src, dst, ety, Ne);

    pack_B_k<<<(NCH * 64 * 64 + NCH * 32 * 64 + 255) / 256, 256>>>(W1, Ws1, W2, Ws2);

    fused1_k<<<MT, 256>>>(feat, b1, Nn);
    fused2_k<<<MT, 256>>>(b2, out, Nn);
}

// round 16
// speedup vs baseline: 1.3195x; 1.0229x over previous
#include <cuda_runtime.h>
#include <cuda_bf16.h>
#include <cstdint>
#include <cstddef>

// Problem constants (fixed by the reference).
#define NN    100000
#define EE    1600000
#define RR    8
#define DIN   64
#define DOUT  32

// GEMM geometry: K = 576 (8 relations x 64 + 64 self-loop), in 9 chunks of 64.
// A/B chunk row = [hi(64) | lo(64) | pad(8)] = 136 bf16 = 272 B;
// 272 % 128 == 16 -> ldmatrix phases conflict-free.
// Error-compensated product: C = Ah*Bh + Al*Bh + Ah*Bl.
#define KSTRIDE 136
#define NCH     9
#define CH_E    (64 * KSTRIDE)     // 8704 elems = 17408 B (A chunk / B1 chunk)
#define CH2_E   (32 * KSTRIDE)     // 4352 elems =  8704 B (B2 chunk)

// CSR over (rel*NN + dst) keys: per (rel, node-range) spans are contiguous.
#define NKEY    (NN * RR)          // 800000
#define SCAN_N2 (NKEY + 1)         // 800001
#define SCAN_B  1024
#define SCAN_NB ((SCAN_N2 + SCAN_B - 1) / SCAN_B)  // 782

// ---------------------------------------------------------------------------
// Scratch (__device__ globals; allocation-free rule).
// ---------------------------------------------------------------------------
__device__ float         g_h1[(size_t)NN * DIN];    // relu(layer1) [N,64] (L2-resident)
__device__ __nv_bfloat16 g_B1s[NCH * CH_E];         // layer-1 B chunks
__device__ __nv_bfloat16 g_B2s[NCH * CH2_E];        // layer-2 B chunks
__device__ int           g_cnt[SCAN_N2];            // CSR offsets
__device__ int           g_pos[NKEY];               // scatter cursors
__device__ int           g_bsum[SCAN_NB];           // scan partials
__device__ int           g_eidx[EE];                // src per edge, bucket-sorted

// ---------------------------------------------------------------------------
// PTX helpers (base sm_103-safe: ldmatrix + mma.sync only).
// ---------------------------------------------------------------------------
__device__ __forceinline__ uint32_t smem_u32(const void* p) {
    uint32_t a;
    asm("{ .reg .u64 t; cvta.to.shared.u64 t, %1; cvt.u32.u64 %0, t; }" : "=r"(a) : "l"(p));
    return a;
}

#define LDSM4(r0, r1, r2, r3, addr)                                             \
    asm volatile("ldmatrix.sync.aligned.m8n8.x4.shared.b16 {%0,%1,%2,%3}, [%4];" \
                 : "=r"(r0), "=r"(r1), "=r"(r2), "=r"(r3) : "r"(addr))

#define MMA16816(c0, c1, c2, c3, a0, a1, a2, a3, b0, b1)                        \
    asm volatile("mma.sync.aligned.m16n8k16.row.col.f32.bf16.bf16.f32 "          \
                 "{%0,%1,%2,%3},{%4,%5,%6,%7},{%8,%9},{%0,%1,%2,%3};"            \
                 : "+f"(c0), "+f"(c1), "+f"(c2), "+f"(c3)                        \
                 : "r"(a0), "r"(a1), "r"(a2), "r"(a3), "r"(b0), "r"(b1))

// ---------------------------------------------------------------------------
// CSR build over (ety*NN + dst).
// ---------------------------------------------------------------------------
__global__ void zero_cnt_k()
{
    int t = blockIdx.x * blockDim.x + threadIdx.x;
    if (t < SCAN_N2) g_cnt[t] = 0;
}

__global__ void hist_k(const int* __restrict__ dst, const int* __restrict__ ety, int Ne)
{
    int e = blockIdx.x * blockDim.x + threadIdx.x;
    if (e < Ne) atomicAdd(&g_cnt[ety[e] * NN + dst[e] + 1], 1);
}

__global__ void scan1_k()
{
    __shared__ int sh[SCAN_B];
    int i = blockIdx.x * SCAN_B + threadIdx.x;
    int v = (i < SCAN_N2) ? g_cnt[i] : 0;
    sh[threadIdx.x] = v;
    __syncthreads();
#pragma unroll
    for (int off = 1; off < SCAN_B; off <<= 1) {
        int t = (threadIdx.x >= off) ? sh[threadIdx.x - off] : 0;
        __syncthreads();
        sh[threadIdx.x] += t;
        __syncthreads();
    }
    if (i < SCAN_N2) g_cnt[i] = sh[threadIdx.x];
    if (threadIdx.x == SCAN_B - 1) g_bsum[blockIdx.x] = sh[SCAN_B - 1];
}

__global__ void scan2_k()
{
    __shared__ int sh[1024];
    int t = threadIdx.x;
    int v = (t < SCAN_NB) ? g_bsum[t] : 0;
    sh[t] = v;
    __syncthreads();
#pragma unroll
    for (int off = 1; off < 1024; off <<= 1) {
        int u = (t >= off) ? sh[t - off] : 0;
        __syncthreads();
        sh[t] += u;
        __syncthreads();
    }
    if (t < SCAN_NB) g_bsum[t] = sh[t] - v;   // exclusive block base
}

__global__ void scan3_k()
{
    int i = blockIdx.x * blockDim.x + threadIdx.x;
    if (i < SCAN_N2) {
        int v = g_cnt[i] + g_bsum[i / SCAN_B];
        g_cnt[i] = v;
        if (i < NKEY) g_pos[i] = v;
    }
}

__global__ void scatter_k(const int* __restrict__ src, const int* __restrict__ dst,
                          const int* __restrict__ ety, int Ne)
{
    int e = blockIdx.x * blockDim.x + threadIdx.x;
    if (e >= Ne) return;
    int p = atomicAdd(&g_pos[ety[e] * NN + dst[e]], 1);
    g_eidx[p] = src[e];
}

// ---------------------------------------------------------------------------
// Pack weights -> B chunks [c][n][hi64|lo64|pad8] bf16.
// ---------------------------------------------------------------------------
__global__ void pack_B_k(const float* __restrict__ W1, const float* __restrict__ Ws1,
                         const float* __restrict__ W2, const float* __restrict__ Ws2)
{
    int u = blockIdx.x * blockDim.x + threadIdx.x;
    const int tot1 = NCH * 64 * 64;      // 36864
    const int tot2 = NCH * 32 * 64;      // 18432
    if (u >= tot1 + tot2) return;
    __nv_bfloat16* row;
    float w;
    int kk;
    if (u < tot1) {
        int c = u >> 12, rem = u & 4095;
        int n = rem >> 6; kk = rem & 63;
        w = (c < 8) ? W1[((size_t)(c * 64 + kk)) * 64 + n]
                    : Ws1[(size_t)kk * 64 + n];
        row = g_B1s + (size_t)c * CH_E + n * KSTRIDE;
    } else {
        int u2 = u - tot1;
        int c = u2 / 2048, rem = u2 % 2048;
        int n = rem >> 6; kk = rem & 63;
        w = (c < 8) ? W2[((size_t)(c * 64 + kk)) * 32 + n]
                    : Ws2[(size_t)kk * 32 + n];
        row = g_B2s + (size_t)c * CH2_E + n * KSTRIDE;
    }
    __nv_bfloat16 h = __float2bfloat16(w);
    __nv_bfloat16 l = __float2bfloat16(w - __bfloat162float(h));
    row[kk]      = h;
    row[64 + kk] = l;
    if (kk < 8) row[128 + kk] = __float2bfloat16(0.f);
}

// ---------------------------------------------------------------------------
// Gather for one 16-lane group: 4 consecutive nodes, one chunk.
// cntS: smem-cached CSR offsets for this CTA tile (8 rels x 65).
// Edges for the 4 nodes are one contiguous eidx span (key = rel*NN + dst).
// ---------------------------------------------------------------------------
__device__ __forceinline__ void fadd4(float4& a, const float4& v)
{
    a.x += v.x; a.y += v.y; a.z += v.z; a.w += v.w;
}

__device__ __forceinline__ void write_split_row(__nv_bfloat16* __restrict__ smA,
                                                int m, int l, const float4& acc)
{
    __nv_bfloat16 hx = __float2bfloat16(acc.x), hy = __float2bfloat16(acc.y);
    __nv_bfloat16 hz = __float2bfloat16(acc.z), hw = __float2bfloat16(acc.w);
    __nv_bfloat162 h01; h01.x = hx; h01.y = hy;
    __nv_bfloat162 h23; h23.x = hz; h23.y = hw;
    __nv_bfloat162 l01; l01.x = __float2bfloat16(acc.x - __bfloat162float(hx));
    l01.y = __float2bfloat16(acc.y - __bfloat162float(hy));
    __nv_bfloat162 l23; l23.x = __float2bfloat16(acc.z - __bfloat162float(hz));
    l23.y = __float2bfloat16(acc.w - __bfloat162float(hw));
    __nv_bfloat16* row = smA + (size_t)m * KSTRIDE;
    *reinterpret_cast<__nv_bfloat162*>(row + l * 4)          = h01;
    *reinterpret_cast<__nv_bfloat162*>(row + l * 4 + 2)      = h23;
    *reinterpret_cast<__nv_bfloat162*>(row + 64 + l * 4)     = l01;
    *reinterpret_cast<__nv_bfloat162*>(row + 64 + l * 4 + 2) = l23;
}

__device__ __forceinline__ void gather_group(const float* __restrict__ X,
                                             const int* __restrict__ cntS,
                                             __nv_bfloat16* __restrict__ smA,
                                             int m0, int g, int l, int c, int Nn,
                                             uint32_t gmask)
{
    float4 a0 = make_float4(0.f, 0.f, 0.f, 0.f);
    float4 a1 = a0, a2 = a0, a3 = a0;
    const int n0 = m0 + 4 * g;

    if (c == 8) {
        if (n0 + 0 < Nn) a0 = *reinterpret_cast<const float4*>(X + (size_t)(n0 + 0) * 64 + l * 4);
        if (n0 + 1 < Nn) a1 = *reinterpret_cast<const float4*>(X + (size_t)(n0 + 1) * 64 + l * 4);
        if (n0 + 2 < Nn) a2 = *reinterpret_cast<const float4*>(X + (size_t)(n0 + 2) * 64 + l * 4);
        if (n0 + 3 < Nn) a3 = *reinterpret_cast<const float4*>(X + (size_t)(n0 + 3) * 64 + l * 4);
    } else {
        const int* bp = cntS + c * 65 + 4 * g;
        int b0 = bp[0], b1 = bp[1], b2 = bp[2], b3 = bp[3], b4 = bp[4];
        int nE = b4 - b0;
        for (int base = 0; base < nE; base += 16) {
            int cnt16 = nE - base; if (cnt16 > 16) cnt16 = 16;
            int my = 0;
            if (base + l < nE) my = __ldg(g_eidx + b0 + base + l);
            for (int j = 0; j < cnt16; j++) {
                int s = __shfl_sync(gmask, my, j, 16);
                float4 v = *reinterpret_cast<const float4*>(X + (size_t)s * 64 + l * 4);
                int ge = b0 + base + j;
                if      (ge < b1) fadd4(a0, v);
                else if (ge < b2) fadd4(a1, v);
                else if (ge < b3) fadd4(a2, v);
                else              fadd4(a3, v);
            }
        }
    }
    write_split_row(smA, 4 * g + 0, l, a0);
    write_split_row(smA, 4 * g + 1, l, a1);
    write_split_row(smA, 4 * g + 2, l, a2);
    write_split_row(smA, 4 * g + 3, l, a3);
}

// Load CSR offsets for this tile into smem: cntS[c][t] = cnt[c*NN + min(m0+t, NN)].
__device__ __forceinline__ void load_cntS(int* __restrict__ cntS, int m0, int tid)
{
    for (int i = tid; i < 8 * 65; i += 256) {
        int c = i / 65, t = i - c * 65;
        int n = m0 + t; if (n > NN) n = NN;
        cntS[i] = __ldg(g_cnt + (size_t)c * NN + n);
    }
}

// Zero the A-tile pad columns (done once; never overwritten).
__device__ __forceinline__ void zero_padA(__nv_bfloat16* __restrict__ smA, int tid)
{
    if (tid < 64) {
        __nv_bfloat162 z; z.x = __float2bfloat16(0.f); z.y = z.x;
        __nv_bfloat16* row = smA + (size_t)tid * KSTRIDE + 128;
#pragma unroll
        for (int q = 0; q < 4; q++)
            *reinterpret_cast<__nv_bfloat162*>(row + 2 * q) = z;
    }
}

// ---------------------------------------------------------------------------
// Fused layer 1: gather -> split A (smem) -> compensated MMA; +bias, relu.
// ---------------------------------------------------------------------------
__global__ void __launch_bounds__(256, 3)
fused1_k(const float* __restrict__ X, const float* __restrict__ b1, int Nn)
{
    __shared__ __nv_bfloat16 sm[2 * CH_E];   // A | B
    __shared__ int cntS[8 * 65];
    const int tid  = threadIdx.x;
    const int lane = tid & 31;
    const int wid  = tid >> 5;
    const int wm   = wid & 3;
    const int wn   = wid >> 2;
    const int m0   = blockIdx.x * 64;
    const int grp  = tid >> 4;
    const int gl   = tid & 15;
    const uint32_t gmask = 0xFFFFu << (lane & 16);

    load_cntS(cntS, m0, tid);
    zero_padA(sm, tid);

    const uint32_t smA = smem_u32(sm);
    const uint32_t smB = smA + CH_E * 2;
    const uint32_t aAddr  = smA + (uint32_t)(wm * 16 + (lane & 15)) * (KSTRIDE * 2)
                          + (uint32_t)((lane >> 4) << 4);
    const uint32_t bAddr0 = smB + (uint32_t)(wn * 32 + ((lane >> 4) << 3) + (lane & 7)) * (KSTRIDE * 2)
                          + (uint32_t)(((lane >> 3) & 1) << 4);
    const uint32_t bAddr1 = bAddr0 + 16 * (KSTRIDE * 2);

    float c[4][4];
#pragma unroll
    for (int i = 0; i < 4; i++)
#pragma unroll
        for (int j = 0; j < 4; j++) c[i][j] = 0.f;

    for (int ch = 0; ch < NCH; ch++) {
        __syncthreads();                     // prior MMA reads done; cntS ready
        {
            const float4* srcB = reinterpret_cast<const float4*>(g_B1s + (size_t)ch * CH_E);
            float4* dstB = reinterpret_cast<float4*>(sm + CH_E);
            for (int i = tid; i < CH_E / 8; i += 256) dstB[i] = srcB[i];
        }
        gather_group(X, cntS, sm, m0, grp, gl, ch, Nn, gmask);
        __syncthreads();

#pragma unroll
        for (int s = 0; s < 12; s++) {
            const int combo = s >> 2;        // 0:(h,h) 1:(l,h) 2:(h,l)
            const int ks    = s & 3;
            const uint32_t ao = (combo == 1 ? 128u : 0u) + (uint32_t)ks * 32u;
            const uint32_t bo = (combo == 2 ? 128u : 0u) + (uint32_t)ks * 32u;
            uint32_t a[4], b0[4], b1v[4];
            LDSM4(a[0], a[1], a[2], a[3], aAddr + ao);
            LDSM4(b0[0], b0[1], b0[2], b0[3], bAddr0 + bo);
            LDSM4(b1v[0], b1v[1], b1v[2], b1v[3], bAddr1 + bo);
            MMA16816(c[0][0], c[0][1], c[0][2], c[0][3], a[0], a[1], a[2], a[3], b0[0], b0[1]);
            MMA16816(c[1][0], c[1][1], c[1][2], c[1][3], a[0], a[1], a[2], a[3], b0[2], b0[3]);
            MMA16816(c[2][0], c[2][1], c[2][2], c[2][3], a[0], a[1], a[2], a[3], b1v[0], b1v[1]);
            MMA16816(c[3][0], c[3][1], c[3][2], c[3][3], a[0], a[1], a[2], a[3], b1v[2], b1v[3]);
        }
    }

    const int colBase = wn * 32 + 2 * (lane & 3);
    const int row0 = m0 + wm * 16 + (lane >> 2);
#pragma unroll
    for (int j = 0; j < 4; j++) {
        int col = colBase + j * 8;
        float bx = __ldg(b1 + col), by = __ldg(b1 + col + 1);
        if (row0 < Nn)
            *reinterpret_cast<float2*>(g_h1 + (size_t)row0 * 64 + col) =
                make_float2(fmaxf(c[j][0] + bx, 0.f), fmaxf(c[j][1] + by, 0.f));
        if (row0 + 8 < Nn)
            *reinterpret_cast<float2*>(g_h1 + (size_t)(row0 + 8) * 64 + col) =
                make_float2(fmaxf(c[j][2] + bx, 0.f), fmaxf(c[j][3] + by, 0.f));
    }
}

// ---------------------------------------------------------------------------
// Fused layer 2: X = g_h1, B2 chunks (32 cols), +bias -> out.
// ---------------------------------------------------------------------------
__global__ void __launch_bounds__(256, 3)
fused2_k(const float* __restrict__ b2, float* __restrict__ out, int Nn)
{
    __shared__ __nv_bfloat16 sm[CH_E + CH2_E];
    __shared__ int cntS[8 * 65];
    const int tid  = threadIdx.x;
    const int lane = tid & 31;
    const int wid  = tid >> 5;
    const int wm   = wid & 3;
    const int wn   = wid >> 2;
    const int m0   = blockIdx.x * 64;
    const int grp  = tid >> 4;
    const int gl   = tid & 15;
    const uint32_t gmask = 0xFFFFu << (lane & 16);

    load_cntS(cntS, m0, tid);
    zero_padA(sm, tid);

    const uint32_t smA = smem_u32(sm);
    const uint32_t smB = smA + CH_E * 2;
    const uint32_t aAddr  = smA + (uint32_t)(wm * 16 + (lane & 15)) * (KSTRIDE * 2)
                          + (uint32_t)((lane >> 4) << 4);
    const uint32_t bAddr0 = smB + (uint32_t)(wn * 16 + ((lane >> 4) << 3) + (lane & 7)) * (KSTRIDE * 2)
                          + (uint32_t)(((lane >> 3) & 1) << 4);

    float c[2][4];
#pragma unroll
    for (int i = 0; i < 2; i++)
#pragma unroll
        for (int j = 0; j < 4; j++) c[i][j] = 0.f;

    for (int ch = 0; ch < NCH; ch++) {
        __syncthreads();
        {
            const float4* srcB = reinterpret_cast<const float4*>(g_B2s + (size_t)ch * CH2_E);
            float4* dstB = reinterpret_cast<float4*>(sm + CH_E);
            for (int i = tid; i < CH2_E / 8; i += 256) dstB[i] = srcB[i];
        }
        gather_group(g_h1, cntS, sm, m0, grp, gl, ch, Nn, gmask);
        __syncthreads();

#pragma unroll
        for (int s = 0; s < 12; s++) {
            const int combo = s >> 2;
            const int ks    = s & 3;
            const uint32_t ao = (combo == 1 ? 128u : 0u) + (uint32_t)ks * 32u;
            const uint32_t bo = (combo == 2 ? 128u : 0u) + (uint32_t)ks * 32u;
            uint32_t a[4], b0[4];
            LDSM4(a[0], a[1], a[2], a[3], aAddr + ao);
            LDSM4(b0[0], b0[1], b0[2], b0[3], bAddr0 + bo);
            MMA16816(c[0][0], c[0][1], c[0][2], c[0][3], a[0], a[1], a[2], a[3], b0[0], b0[1]);
            MMA16816(c[1][0], c[1][1], c[1][2], c[1][3], a[0], a[1], a[2], a[3], b0[2], b0[3]);
        }
    }

    const int colBase = wn * 16 + 2 * (lane & 3);
    const int row0 = m0 + wm * 16 + (lane >> 2);
#pragma unroll
    for (int j = 0; j < 2; j++) {
        int col = colBase + j * 8;
        float bx = __ldg(b2 + col), by = __ldg(b2 + col + 1);
        if (row0 < Nn)
            *reinterpret_cast<float2*>(out + (size_t)row0 * 32 + col) =
                make_float2(c[j][0] + bx, c[j][1] + by);
        if (row0 + 8 < Nn)
            *reinterpret_cast<float2*>(out + (size_t)(row0 + 8) * 32 + col) =
                make_float2(c[j][2] + bx, c[j][3] + by);
    }
}

// ---------------------------------------------------------------------------
// kernel_launch
// ---------------------------------------------------------------------------
extern "C" void kernel_launch(void* const* d_in, const int* in_sizes, int n_in,
                              void* d_out, int out_size)
{
    const float* feat = (const float*)d_in[0];
    const int*   src  = (const int*)  d_in[1];
    const int*   dst  = (const int*)  d_in[2];
    const int*   ety  = (const int*)  d_in[3];
    const float* W1   = (const float*)d_in[4];
    const float* Ws1  = (const float*)d_in[5];
    const float* b1   = (const float*)d_in[6];
    const float* W2   = (const float*)d_in[7];
    const float* Ws2  = (const float*)d_in[8];
    const float* b2   = (const float*)d_in[9];
    float* out = (float*)d_out;

    int Nn = in_sizes[0] / DIN;
    int Ne = in_sizes[1];
    int MT = (Nn + 63) / 64;

    // CSR over (rel, dst).
    zero_cnt_k<<<(SCAN_N2 + 255) / 256, 256>>>();
    hist_k<<<(Ne + 255) / 256, 256>>>(dst, ety, Ne);
    scan1_k<<<SCAN_NB, SCAN_B>>>();
    scan2_k<<<1, 1024>>>();
    scan3_k<<<(SCAN_N2 + 255) / 256, 256>>>();
    scatter_k<<<(Ne + 255) / 256, 256>>>(src, dst, ety, Ne);

    pack_B_k<<<(NCH * 64 * 64 + NCH * 32 * 64 + 255) / 256, 256>>>(W1, Ws1, W2, Ws2);

    fused1_k<<<MT, 256>>>(feat, b1, Nn);
    fused2_k<<<MT, 256>>>(b2, out, Nn);
}

// round 17
// speedup vs baseline: 1.3873x; 1.0514x over previous
#include <cuda_runtime.h>
#include <cuda_fp16.h>
#include <cstdint>
#include <cstddef>

// Problem constants (fixed by the reference).
#define NN    100000
#define EE    1600000
#define RR    8
#define DIN   64
#define DOUT  32

// GEMM geometry: K = 576 (8 relations x 64 + 64 self-loop), in 9 chunks of 64.
// A chunk row = [Ah(64) | Al(64) | pad(8)] fp16 = 272 B (272%128==16: conflict-free).
// B chunk row = [B(64) | pad(8)] fp16 = 144 B (144%128==16: conflict-free).
// fp16 2-term compensated product: C = Ah*B + Al*B  (A error ~2^-22; B single
// fp16 half-ulp 2^-11 -> expected output rel_err ~3e-4 < 1e-3).
#define KSTRIDE  136
#define KSTRB    72
#define NCH      9
#define CH_E     (64 * KSTRIDE)    // A chunk: 8704 halves = 17408 B
#define CHB1_E   (64 * KSTRB)      // B1 chunk: 4608 halves = 9216 B
#define CHB2_E   (32 * KSTRB)      // B2 chunk: 2304 halves = 4608 B

// CSR over (rel*NN + dst) keys: per (rel, node-range) spans are contiguous.
#define NKEY    (NN * RR)          // 800000
#define SCAN_N2 (NKEY + 1)         // 800001
#define SCAN_B  1024
#define SCAN_NB ((SCAN_N2 + SCAN_B - 1) / SCAN_B)  // 782

// ---------------------------------------------------------------------------
// Scratch (__device__ globals; allocation-free rule).
// ---------------------------------------------------------------------------
__device__ float  g_h1[(size_t)NN * DIN];   // relu(layer1) [N,64] (L2-resident)
__device__ __half g_B1s[NCH * CHB1_E];      // layer-1 B chunks (fp16)
__device__ __half g_B2s[NCH * CHB2_E];      // layer-2 B chunks (fp16)
__device__ int    g_cnt[SCAN_N2];           // CSR offsets
__device__ int    g_pos[NKEY];              // scatter cursors
__device__ int    g_bsum[SCAN_NB];          // scan partials
__device__ int    g_eidx[EE];               // src per edge, bucket-sorted

// ---------------------------------------------------------------------------
// PTX helpers (base sm_103-safe: ldmatrix + mma.sync only).
// ---------------------------------------------------------------------------
__device__ __forceinline__ uint32_t smem_u32(const void* p) {
    uint32_t a;
    asm("{ .reg .u64 t; cvta.to.shared.u64 t, %1; cvt.u32.u64 %0, t; }" : "=r"(a) : "l"(p));
    return a;
}

#define LDSM4(r0, r1, r2, r3, addr)                                             \
    asm volatile("ldmatrix.sync.aligned.m8n8.x4.shared.b16 {%0,%1,%2,%3}, [%4];" \
                 : "=r"(r0), "=r"(r1), "=r"(r2), "=r"(r3) : "r"(addr))

#define MMAF16(c0, c1, c2, c3, a0, a1, a2, a3, b0, b1)                          \
    asm volatile("mma.sync.aligned.m16n8k16.row.col.f32.f16.f16.f32 "            \
                 "{%0,%1,%2,%3},{%4,%5,%6,%7},{%8,%9},{%0,%1,%2,%3};"            \
                 : "+f"(c0), "+f"(c1), "+f"(c2), "+f"(c3)                        \
                 : "r"(a0), "r"(a1), "r"(a2), "r"(a3), "r"(b0), "r"(b1))

// ---------------------------------------------------------------------------
// CSR build over (ety*NN + dst).
// ---------------------------------------------------------------------------
__global__ void zero_cnt_k()
{
    int t = blockIdx.x * blockDim.x + threadIdx.x;
    if (t < SCAN_N2) g_cnt[t] = 0;
}

__global__ void hist_k(const int* __restrict__ dst, const int* __restrict__ ety, int Ne)
{
    int e = blockIdx.x * blockDim.x + threadIdx.x;
    if (e < Ne) atomicAdd(&g_cnt[ety[e] * NN + dst[e] + 1], 1);
}

__global__ void scan1_k()
{
    __shared__ int sh[SCAN_B];
    int i = blockIdx.x * SCAN_B + threadIdx.x;
    int v = (i < SCAN_N2) ? g_cnt[i] : 0;
    sh[threadIdx.x] = v;
    __syncthreads();
#pragma unroll
    for (int off = 1; off < SCAN_B; off <<= 1) {
        int t = (threadIdx.x >= off) ? sh[threadIdx.x - off] : 0;
        __syncthreads();
        sh[threadIdx.x] += t;
        __syncthreads();
    }
    if (i < SCAN_N2) g_cnt[i] = sh[threadIdx.x];
    if (threadIdx.x == SCAN_B - 1) g_bsum[blockIdx.x] = sh[SCAN_B - 1];
}

__global__ void scan2_k()
{
    __shared__ int sh[1024];
    int t = threadIdx.x;
    int v = (t < SCAN_NB) ? g_bsum[t] : 0;
    sh[t] = v;
    __syncthreads();
#pragma unroll
    for (int off = 1; off < 1024; off <<= 1) {
        int u = (t >= off) ? sh[t - off] : 0;
        __syncthreads();
        sh[t] += u;
        __syncthreads();
    }
    if (t < SCAN_NB) g_bsum[t] = sh[t] - v;   // exclusive block base
}

__global__ void scan3_k()
{
    int i = blockIdx.x * blockDim.x + threadIdx.x;
    if (i < SCAN_N2) {
        int v = g_cnt[i] + g_bsum[i / SCAN_B];
        g_cnt[i] = v;
        if (i < NKEY) g_pos[i] = v;
    }
}

__global__ void scatter_k(const int* __restrict__ src, const int* __restrict__ dst,
                          const int* __restrict__ ety, int Ne)
{
    int e = blockIdx.x * blockDim.x + threadIdx.x;
    if (e >= Ne) return;
    int p = atomicAdd(&g_pos[ety[e] * NN + dst[e]], 1);
    g_eidx[p] = src[e];
}

// ---------------------------------------------------------------------------
// Pack weights -> fp16 B chunks [c][n][64|pad8].
// ---------------------------------------------------------------------------
__global__ void pack_B_k(const float* __restrict__ W1, const float* __restrict__ Ws1,
                         const float* __restrict__ W2, const float* __restrict__ Ws2)
{
    int u = blockIdx.x * blockDim.x + threadIdx.x;
    const int tot1 = NCH * 64 * 64;      // 36864
    const int tot2 = NCH * 32 * 64;      // 18432
    if (u >= tot1 + tot2) return;
    __half* row;
    float w;
    int kk;
    if (u < tot1) {
        int c = u >> 12, rem = u & 4095;
        int n = rem >> 6; kk = rem & 63;
        w = (c < 8) ? W1[((size_t)(c * 64 + kk)) * 64 + n]
                    : Ws1[(size_t)kk * 64 + n];
        row = g_B1s + (size_t)c * CHB1_E + n * KSTRB;
    } else {
        int u2 = u - tot1;
        int c = u2 / 2048, rem = u2 % 2048;
        int n = rem >> 6; kk = rem & 63;
        w = (c < 8) ? W2[((size_t)(c * 64 + kk)) * 32 + n]
                    : Ws2[(size_t)kk * 32 + n];
        row = g_B2s + (size_t)c * CHB2_E + n * KSTRB;
    }
    row[kk] = __float2half_rn(w);
    if (kk < 8) row[64 + kk] = __float2half_rn(0.f);
}

// ---------------------------------------------------------------------------
// Gather helpers.
// ---------------------------------------------------------------------------
__device__ __forceinline__ void fadd4(float4& a, const float4& v)
{
    a.x += v.x; a.y += v.y; a.z += v.z; a.w += v.w;
}

// fp16 split write: row[l*4..] = Ah pair x2, row[64+l*4..] = Al pair x2.
__device__ __forceinline__ void write_split_row(__half* __restrict__ smA,
                                                int m, int l, const float4& acc)
{
    float hx = __half2float(__float2half_rn(acc.x));
    float hy = __half2float(__float2half_rn(acc.y));
    float hz = __half2float(__float2half_rn(acc.z));
    float hw = __half2float(__float2half_rn(acc.w));
    uint32_t h01 = (uint32_t)__half_as_ushort(__float2half_rn(acc.x))
                 | ((uint32_t)__half_as_ushort(__float2half_rn(acc.y)) << 16);
    uint32_t h23 = (uint32_t)__half_as_ushort(__float2half_rn(acc.z))
                 | ((uint32_t)__half_as_ushort(__float2half_rn(acc.w)) << 16);
    uint32_t l01 = (uint32_t)__half_as_ushort(__float2half_rn(acc.x - hx))
                 | ((uint32_t)__half_as_ushort(__float2half_rn(acc.y - hy)) << 16);
    uint32_t l23 = (uint32_t)__half_as_ushort(__float2half_rn(acc.z - hz))
                 | ((uint32_t)__half_as_ushort(__float2half_rn(acc.w - hw)) << 16);
    uint32_t* row = reinterpret_cast<uint32_t*>(smA + (size_t)m * KSTRIDE);
    row[l]          = h01;
    row[l + 1 + l]  = 0;  // placeholder never used; overwritten below
    // (avoid compiler confusion: write directly)
    row[2 * l]      = h01;
    row[2 * l + 1]  = h23;
    row[32 + 2 * l]     = l01;
    row[32 + 2 * l + 1] = l23;
}

__device__ __forceinline__ void gather_group(const float* __restrict__ X,
                                             const int* __restrict__ cntS,
                                             __half* __restrict__ smA,
                                             int m0, int g, int l, int c, int Nn,
                                             uint32_t gmask)
{
    float4 a0 = make_float4(0.f, 0.f, 0.f, 0.f);
    float4 a1 = a0, a2 = a0, a3 = a0;
    const int n0 = m0 + 4 * g;

    if (c == 8) {
        if (n0 + 0 < Nn) a0 = *reinterpret_cast<const float4*>(X + (size_t)(n0 + 0) * 64 + l * 4);
        if (n0 + 1 < Nn) a1 = *reinterpret_cast<const float4*>(X + (size_t)(n0 + 1) * 64 + l * 4);
        if (n0 + 2 < Nn) a2 = *reinterpret_cast<const float4*>(X + (size_t)(n0 + 2) * 64 + l * 4);
        if (n0 + 3 < Nn) a3 = *reinterpret_cast<const float4*>(X + (size_t)(n0 + 3) * 64 + l * 4);
    } else {
        const int* bp = cntS + c * 65 + 4 * g;
        int b0 = bp[0], b1 = bp[1], b2 = bp[2], b3 = bp[3], b4 = bp[4];
        int nE = b4 - b0;
        for (int base = 0; base < nE; base += 16) {
            int cnt16 = nE - base; if (cnt16 > 16) cnt16 = 16;
            int my = 0;
            if (base + l < nE) my = __ldg(g_eidx + b0 + base + l);
            for (int j = 0; j < cnt16; j++) {
                int s = __shfl_sync(gmask, my, j, 16);
                float4 v = *reinterpret_cast<const float4*>(X + (size_t)s * 64 + l * 4);
                int ge = b0 + base + j;
                if      (ge < b1) fadd4(a0, v);
                else if (ge < b2) fadd4(a1, v);
                else if (ge < b3) fadd4(a2, v);
                else              fadd4(a3, v);
            }
        }
    }
    write_split_row(smA, 4 * g + 0, l, a0);
    write_split_row(smA, 4 * g + 1, l, a1);
    write_split_row(smA, 4 * g + 2, l, a2);
    write_split_row(smA, 4 * g + 3, l, a3);
}

// Load CSR offsets for this tile into smem: cntS[c][t] = cnt[c*NN + min(m0+t, NN)].
__device__ __forceinline__ void load_cntS(int* __restrict__ cntS, int m0, int tid)
{
    for (int i = tid; i < 8 * 65; i += 256) {
        int c = i / 65, t = i - c * 65;
        int n = m0 + t; if (n > NN) n = NN;
        cntS[i] = __ldg(g_cnt + (size_t)c * NN + n);
    }
}

// Zero the A-tile pad columns (elems 128..135 per row; done once).
__device__ __forceinline__ void zero_padA(__half* __restrict__ smA, int tid)
{
    if (tid < 64) {
        uint32_t* row = reinterpret_cast<uint32_t*>(smA + (size_t)tid * KSTRIDE);
#pragma unroll
        for (int q = 0; q < 4; q++) row[64 + q] = 0;
    }
}

// ---------------------------------------------------------------------------
// Fused layer 1: gather -> fp16-split A (smem) -> 2-term MMA; +bias, relu.
// Per chunk: 4 ksteps; per kstep: LDSM B(x2), Ah, Al; 8 MMA (B regs reused).
// ---------------------------------------------------------------------------
__global__ void __launch_bounds__(256, 3)
fused1_k(const float* __restrict__ X, const float* __restrict__ b1, int Nn)
{
    __shared__ __half sm[CH_E + CHB1_E];   // A | B  (17408 + 9216 = 26624 B)
    __shared__ int cntS[8 * 65];
    const int tid  = threadIdx.x;
    const int lane = tid & 31;
    const int wid  = tid >> 5;
    const int wm   = wid & 3;
    const int wn   = wid >> 2;
    const int m0   = blockIdx.x * 64;
    const int grp  = tid >> 4;
    const int gl   = tid & 15;
    const uint32_t gmask = 0xFFFFu << (lane & 16);

    load_cntS(cntS, m0, tid);
    zero_padA(sm, tid);

    const uint32_t smA = smem_u32(sm);
    const uint32_t smB = smA + CH_E * 2;
    const uint32_t aAddr  = smA + (uint32_t)(wm * 16 + (lane & 15)) * (KSTRIDE * 2)
                          + (uint32_t)((lane >> 4) << 4);
    const uint32_t bAddr0 = smB + (uint32_t)(wn * 32 + ((lane >> 4) << 3) + (lane & 7)) * (KSTRB * 2)
                          + (uint32_t)(((lane >> 3) & 1) << 4);
    const uint32_t bAddr1 = bAddr0 + 16 * (KSTRB * 2);

    float c[4][4];
#pragma unroll
    for (int i = 0; i < 4; i++)
#pragma unroll
        for (int j = 0; j < 4; j++) c[i][j] = 0.f;

    for (int ch = 0; ch < NCH; ch++) {
        __syncthreads();                     // prior MMA reads done; cntS ready
        {
            const float4* srcB = reinterpret_cast<const float4*>(g_B1s + (size_t)ch * CHB1_E);
            float4* dstB = reinterpret_cast<float4*>(sm + CH_E);
            for (int i = tid; i < CHB1_E / 8; i += 256) dstB[i] = srcB[i];
        }
        gather_group(X, cntS, sm, m0, grp, gl, ch, Nn, gmask);
        __syncthreads();

#pragma unroll
        for (int ks = 0; ks < 4; ks++) {
            const uint32_t ko = (uint32_t)ks * 32u;
            uint32_t b0[4], b1v[4], ah[4], al[4];
            LDSM4(b0[0], b0[1], b0[2], b0[3], bAddr0 + ko);
            LDSM4(b1v[0], b1v[1], b1v[2], b1v[3], bAddr1 + ko);
            LDSM4(ah[0], ah[1], ah[2], ah[3], aAddr + ko);
            LDSM4(al[0], al[1], al[2], al[3], aAddr + 128u + ko);
            MMAF16(c[0][0], c[0][1], c[0][2], c[0][3], ah[0], ah[1], ah[2], ah[3], b0[0], b0[1]);
            MMAF16(c[1][0], c[1][1], c[1][2], c[1][3], ah[0], ah[1], ah[2], ah[3], b0[2], b0[3]);
            MMAF16(c[2][0], c[2][1], c[2][2], c[2][3], ah[0], ah[1], ah[2], ah[3], b1v[0], b1v[1]);
            MMAF16(c[3][0], c[3][1], c[3][2], c[3][3], ah[0], ah[1], ah[2], ah[3], b1v[2], b1v[3]);
            MMAF16(c[0][0], c[0][1], c[0][2], c[0][3], al[0], al[1], al[2], al[3], b0[0], b0[1]);
            MMAF16(c[1][0], c[1][1], c[1][2], c[1][3], al[0], al[1], al[2], al[3], b0[2], b0[3]);
            MMAF16(c[2][0], c[2][1], c[2][2], c[2][3], al[0], al[1], al[2], al[3], b1v[0], b1v[1]);
            MMAF16(c[3][0], c[3][1], c[3][2], c[3][3], al[0], al[1], al[2], al[3], b1v[2], b1v[3]);
        }
    }

    const int colBase = wn * 32 + 2 * (lane & 3);
    const int row0 = m0 + wm * 16 + (lane >> 2);
#pragma unroll
    for (int j = 0; j < 4; j++) {
        int col = colBase + j * 8;
        float bx = __ldg(b1 + col), by = __ldg(b1 + col + 1);
        if (row0 < Nn)
            *reinterpret_cast<float2*>(g_h1 + (size_t)row0 * 64 + col) =
                make_float2(fmaxf(c[j][0] + bx, 0.f), fmaxf(c[j][1] + by, 0.f));
        if (row0 + 8 < Nn)
            *reinterpret_cast<float2*>(g_h1 + (size_t)(row0 + 8) * 64 + col) =
                make_float2(fmaxf(c[j][2] + bx, 0.f), fmaxf(c[j][3] + by, 0.f));
    }
}

// ---------------------------------------------------------------------------
// Fused layer 2: X = g_h1, B2 chunks (32 cols), +bias -> out.
// ---------------------------------------------------------------------------
__global__ void __launch_bounds__(256, 3)
fused2_k(const float* __restrict__ b2, float* __restrict__ out, int Nn)
{
    __shared__ __half sm[CH_E + CHB2_E];   // 17408 + 4608 = 22016 B
    __shared__ int cntS[8 * 65];
    const int tid  = threadIdx.x;
    const int lane = tid & 31;
    const int wid  = tid >> 5;
    const int wm   = wid & 3;
    const int wn   = wid >> 2;
    const int m0   = blockIdx.x * 64;
    const int grp  = tid >> 4;
    const int gl   = tid & 15;
    const uint32_t gmask = 0xFFFFu << (lane & 16);

    load_cntS(cntS, m0, tid);
    zero_padA(sm, tid);

    const uint32_t smA = smem_u32(sm);
    const uint32_t smB = smA + CH_E * 2;
    const uint32_t aAddr  = smA + (uint32_t)(wm * 16 + (lane & 15)) * (KSTRIDE * 2)
                          + (uint32_t)((lane >> 4) << 4);
    const uint32_t bAddr0 = smB + (uint32_t)(wn * 16 + ((lane >> 4) << 3) + (lane & 7)) * (KSTRB * 2)
                          + (uint32_t)(((lane >> 3) & 1) << 4);

    float c[2][4];
#pragma unroll
    for (int i = 0; i < 2; i++)
#pragma unroll
        for (int j = 0; j < 4; j++) c[i][j] = 0.f;

    for (int ch = 0; ch < NCH; ch++) {
        __syncthreads();
        {
            const float4* srcB = reinterpret_cast<const float4*>(g_B2s + (size_t)ch * CHB2_E);
            float4* dstB = reinterpret_cast<float4*>(sm + CH_E);
            for (int i = tid; i < CHB2_E / 8; i += 256) dstB[i] = srcB[i];
        }
        gather_group(g_h1, cntS, sm, m0, grp, gl, ch, Nn, gmask);
        __syncthreads();

#pragma unroll
        for (int ks = 0; ks < 4; ks++) {
            const uint32_t ko = (uint32_t)ks * 32u;
            uint32_t b0[4], ah[4], al[4];
            LDSM4(b0[0], b0[1], b0[2], b0[3], bAddr0 + ko);
            LDSM4(ah[0], ah[1], ah[2], ah[3], aAddr + ko);
            LDSM4(al[0], al[1], al[2], al[3], aAddr + 128u + ko);
            MMAF16(c[0][0], c[0][1], c[0][2], c[0][3], ah[0], ah[1], ah[2], ah[3], b0[0], b0[1]);
            MMAF16(c[1][0], c[1][1], c[1][2], c[1][3], ah[0], ah[1], ah[2], ah[3], b0[2], b0[3]);
            MMAF16(c[0][0], c[0][1], c[0][2], c[0][3], al[0], al[1], al[2], al[3], b0[0], b0[1]);
            MMAF16(c[1][0], c[1][1], c[1][2], c[1][3], al[0], al[1], al[2], al[3], b0[2], b0[3]);
        }
    }

    const int colBase = wn * 16 + 2 * (lane & 3);
    const int row0 = m0 + wm * 16 + (lane >> 2);
#pragma unroll
    for (int j = 0; j < 2; j++) {
        int col = colBase + j * 8;
        float bx = __ldg(b2 + col), by = __ldg(b2 + col + 1);
        if (row0 < Nn)
            *reinterpret_cast<float2*>(out + (size_t)row0 * 32 + col) =
                make_float2(c[j][0] + bx, c[j][1] + by);
        if (row0 + 8 < Nn)
            *reinterpret_cast<float2*>(out + (size_t)(row0 + 8) * 32 + col) =
                make_float2(c[j][2] + bx, c[j][3] + by);
    }
}

// ---------------------------------------------------------------------------
// kernel_launch
// ---------------------------------------------------------------------------
extern "C" void kernel_launch(void* const* d_in, const int* in_sizes, int n_in,
                              void* d_out, int out_size)
{
    const float* feat = (const float*)d_in[0];
    const int*   src  = (const int*)  d_in[1];
    const int*   dst  = (const int*)  d_in[2];
    const int*   ety  = (const int*)  d_in[3];
    const float* W1   = (const float*)d_in[4];
    const float* Ws1  = (const float*)d_in[5];
    const float* b1   = (const float*)d_in[6];
    const float* W2   = (const float*)d_in[7];
    const float* Ws2  = (const float*)d_in[8];
    const float* b2   = (const float*)d_in[9];
    float* out = (float*)d_out;

    int Nn = in_sizes[0] / DIN;
    int Ne = in_sizes[1];
    int MT = (Nn + 63) / 64;

    // CSR over (rel, dst).
    zero_cnt_k<<<(SCAN_N2 + 255) / 256, 256>>>();
    hist_k<<<(Ne + 255) / 256, 256>>>(dst, ety, Ne);
    scan1_k<<<SCAN_NB, SCAN_B>>>();
    scan2_k<<<1, 1024>>>();
    scan3_k<<<(SCAN_N2 + 255) / 256, 256>>>();
    scatter_k<<<(Ne + 255) / 256, 256>>>(src, dst, ety, Ne);

    pack_B_k<<<(NCH * 64 * 64 + NCH * 32 * 64 + 255) / 256, 256>>>(W1, Ws1, W2, Ws2);

    fused1_k<<<MT, 256>>>(feat, b1, Nn);
    fused2_k<<<MT, 256>>>(b2, out, Nn);
}